// round 1
// baseline (speedup 1.0000x reference)
#include <cuda_runtime.h>

// ---------------------------------------------------------------------------
// Temporal attention, B=2, H=W=64, C=128, GROUPS=8 (cg=16), K=7, PAD=3, REFINE
//
// Stage 1: conv1x1 GEMMs  -> g_Q, g_K, g_V  (layout [ch][b*4096 + h*64 + w])
// Stage 2: fused windowed attention (2D 7x7 + row 15 + col 15) per (b,g,tile)
// ---------------------------------------------------------------------------

#define HH   64
#define WW   64
#define BB   2
#define NCH  128
#define NPOS 8192            // BB*HH*WW

// scratch maps (device globals: no allocation allowed)
__device__ float g_Q[NCH * NPOS];
__device__ float g_K[NCH * NPOS];
__device__ float g_V[NCH * NPOS];

// ---------------------------------------------------------------------------
// Stage 1: C[o][p] = sum_c W[o][c] * X[c][p]   (per map z: 0=K,1=V,2=Q)
// M=128 (2 tiles of 64), N=8192 (128 tiles of 64), Kdim=128 (8 chunks of 16)
// ---------------------------------------------------------------------------
__global__ void __launch_bounds__(256) conv_gemm_kernel(
    const float* __restrict__ fm,
    const float* __restrict__ wq,
    const float* __restrict__ wk,
    const float* __restrict__ wv)
{
    const int z = blockIdx.z;
    const float* Wm = (z == 0) ? wk : (z == 1) ? wv : wq;
    float* C        = (z == 0) ? g_K : (z == 1) ? g_V : g_Q;
    const int cbase = (z == 2) ? 128 : 0;     // Q reads fm_t1, K/V read fm_t0

    const int p0 = blockIdx.x * 64;
    const int o0 = blockIdx.y * 64;
    const int b   = p0 >> 12;                 // 4096 positions per batch
    const int hw0 = p0 & 4095;
    const float* Xbase = fm + (size_t)b * (256 * 4096) + (size_t)cbase * 4096 + hw0;

    __shared__ float As[16][68];              // [k][o], padded
    __shared__ float Bs[16][64];              // [k][p]

    const int tid  = threadIdx.x;
    const int tx   = tid & 15;                // p micro-tile
    const int ty   = tid >> 4;                // o micro-tile
    const int a_row = tid >> 2, a_kg = tid & 3;
    const int b_row = tid >> 4, b_cg = tid & 15;

    float acc[4][4];
#pragma unroll
    for (int i = 0; i < 4; i++)
#pragma unroll
        for (int j = 0; j < 4; j++) acc[i][j] = 0.f;

    for (int k0 = 0; k0 < 128; k0 += 16) {
        float4 aw = *(const float4*)(Wm + (o0 + a_row) * 128 + k0 + a_kg * 4);
        As[a_kg * 4 + 0][a_row] = aw.x;
        As[a_kg * 4 + 1][a_row] = aw.y;
        As[a_kg * 4 + 2][a_row] = aw.z;
        As[a_kg * 4 + 3][a_row] = aw.w;
        *(float4*)&Bs[b_row][b_cg * 4] =
            *(const float4*)(Xbase + (size_t)(k0 + b_row) * 4096 + b_cg * 4);
        __syncthreads();
#pragma unroll
        for (int kk = 0; kk < 16; kk++) {
            float4 a  = *(const float4*)&As[kk][ty * 4];
            float4 bq = *(const float4*)&Bs[kk][tx * 4];
            acc[0][0] += a.x * bq.x; acc[0][1] += a.x * bq.y;
            acc[0][2] += a.x * bq.z; acc[0][3] += a.x * bq.w;
            acc[1][0] += a.y * bq.x; acc[1][1] += a.y * bq.y;
            acc[1][2] += a.y * bq.z; acc[1][3] += a.y * bq.w;
            acc[2][0] += a.z * bq.x; acc[2][1] += a.z * bq.y;
            acc[2][2] += a.z * bq.z; acc[2][3] += a.z * bq.w;
            acc[3][0] += a.w * bq.x; acc[3][1] += a.w * bq.y;
            acc[3][2] += a.w * bq.z; acc[3][3] += a.w * bq.w;
        }
        __syncthreads();
    }

    float* Cp = C + (size_t)(o0 + ty * 4) * NPOS + p0 + tx * 4;
#pragma unroll
    for (int i = 0; i < 4; i++) {
        float4 v = make_float4(acc[i][0], acc[i][1], acc[i][2], acc[i][3]);
        *(float4*)(Cp + (size_t)i * NPOS) = v;
    }
}

// ---------------------------------------------------------------------------
// Stage 2: attention. One block = (b, g, 8x16 spatial tile), 128 threads
// (1 thread = 1 position). K/V tiles with +/-7 halo in smem, layout
// [y][x][c] with per-(y,x) stride 20 floats (16B-aligned, conflict-free).
// ---------------------------------------------------------------------------
#define TILE_H 8
#define TILE_W 16
#define EHE    (TILE_H + 14)   // 22
#define EWE    (TILE_W + 14)   // 30
#define CST    20              // 16 channels + 4 pad floats

__global__ void __launch_bounds__(128) attn_kernel(
    const float* __restrict__ relh,
    const float* __restrict__ relw,
    float* __restrict__ out)
{
    extern __shared__ float sm[];
    float* Ks = sm;
    float* Vs = sm + EHE * EWE * CST;

    const int bz = blockIdx.z;          // b*8 + g
    const int b  = bz >> 3;
    const int g  = bz & 7;
    const int y0 = blockIdx.y * TILE_H;
    const int x0 = blockIdx.x * TILE_W;
    const int ch0 = g * 16;
    const int tid = threadIdx.x;

    // ---- load extended K/V tiles (zero outside image) ----
    const float* Kbase = g_K + (size_t)ch0 * NPOS + b * 4096;
    const float* Vbase = g_V + (size_t)ch0 * NPOS + b * 4096;
    for (int idx = tid; idx < EHE * EWE * 16; idx += 128) {
        int c   = idx / (EHE * EWE);
        int rem = idx - c * (EHE * EWE);
        int yy  = rem / EWE;
        int xx  = rem - yy * EWE;
        int gy = y0 + yy - 7, gx = x0 + xx - 7;
        float kv = 0.f, vv = 0.f;
        if ((unsigned)gy < (unsigned)HH && (unsigned)gx < (unsigned)WW) {
            int off = c * NPOS + gy * WW + gx;
            kv = Kbase[off];
            vv = Vbase[off];
        }
        int s = (yy * EWE + xx) * CST + c;
        Ks[s] = kv;
        Vs[s] = vv;
    }
    __syncthreads();

    const int px = tid & 15, py = tid >> 4;
    const int h = y0 + py, w = x0 + px;

    // ---- per-thread query (16 channels) ----
    float q[16];
    const float* Qp = g_Q + (size_t)ch0 * NPOS + b * 4096 + h * WW + w;
#pragma unroll
    for (int c = 0; c < 16; c++) q[c] = Qp[(size_t)c * NPOS];

    // ---- rel bias: g<4 -> rel_h (indexed by dy), g>=4 -> rel_w (by dx) ----
    const bool use_h = (g < 4);
    const float* rel = use_h ? (relh + ch0 * 7) : (relw + (ch0 - 64) * 7);
    float bias[7];
#pragma unroll
    for (int i = 0; i < 7; i++) {
        float s = 0.f;
#pragma unroll
        for (int c = 0; c < 16; c++) s += q[c] * __ldg(&rel[c * 7 + i]);
        bias[i] = s;
    }

    // ---- 2D 7x7 logits ----
    float lg[49];
    float m2 = -1e30f;
#pragma unroll
    for (int dy = 0; dy < 7; dy++) {
#pragma unroll
        for (int dx = 0; dx < 7; dx++) {
            const float* kp = &Ks[((py + 4 + dy) * EWE + (px + 4 + dx)) * CST];
            float s = use_h ? bias[dy] : bias[dx];
#pragma unroll
            for (int c4 = 0; c4 < 4; c4++) {
                float4 k4 = *(const float4*)(kp + c4 * 4);
                s += q[c4 * 4 + 0] * k4.x + q[c4 * 4 + 1] * k4.y +
                     q[c4 * 4 + 2] * k4.z + q[c4 * 4 + 3] * k4.w;
            }
            lg[dy * 7 + dx] = s;
            m2 = fmaxf(m2, s);
        }
    }

    // ---- row (w-7..w+7) and col (h-7..h+7) logits, no bias ----
    float lr[15], lc[15];
    float mr = -1e30f, mc = -1e30f;
#pragma unroll
    for (int j = 0; j < 15; j++) {
        const float* kp = &Ks[((py + 7) * EWE + (px + j)) * CST];
        float s = 0.f;
#pragma unroll
        for (int c4 = 0; c4 < 4; c4++) {
            float4 k4 = *(const float4*)(kp + c4 * 4);
            s += q[c4 * 4 + 0] * k4.x + q[c4 * 4 + 1] * k4.y +
                 q[c4 * 4 + 2] * k4.z + q[c4 * 4 + 3] * k4.w;
        }
        lr[j] = s;
        mr = fmaxf(mr, s);
    }
#pragma unroll
    for (int i = 0; i < 15; i++) {
        const float* kp = &Ks[((py + i) * EWE + (px + 7)) * CST];
        float s = 0.f;
#pragma unroll
        for (int c4 = 0; c4 < 4; c4++) {
            float4 k4 = *(const float4*)(kp + c4 * 4);
            s += q[c4 * 4 + 0] * k4.x + q[c4 * 4 + 1] * k4.y +
                 q[c4 * 4 + 2] * k4.z + q[c4 * 4 + 3] * k4.w;
        }
        lc[i] = s;
        mc = fmaxf(mc, s);
    }

    // ---- softmaxes (normalize weights in place) ----
    float s2 = 0.f, sr = 0.f, sc = 0.f;
#pragma unroll
    for (int k = 0; k < 49; k++) { float e = __expf(lg[k] - m2); lg[k] = e; s2 += e; }
#pragma unroll
    for (int k = 0; k < 15; k++) { float e = __expf(lr[k] - mr); lr[k] = e; sr += e; }
#pragma unroll
    for (int k = 0; k < 15; k++) { float e = __expf(lc[k] - mc); lc[k] = e; sc += e; }
    const float i2 = 1.f / s2, ir = 1.f / sr, ic = 1.f / sc;
#pragma unroll
    for (int k = 0; k < 49; k++) lg[k] *= i2;
#pragma unroll
    for (int k = 0; k < 15; k++) { lr[k] *= ir; lc[k] *= ic; }

    // ---- weighted V accumulation (79 window positions, 16 channels) ----
    float acc[16];
#pragma unroll
    for (int c = 0; c < 16; c++) acc[c] = 0.f;

#pragma unroll
    for (int dy = 0; dy < 7; dy++) {
#pragma unroll
        for (int dx = 0; dx < 7; dx++) {
            float wt = lg[dy * 7 + dx];
            const float* vp = &Vs[((py + 4 + dy) * EWE + (px + 4 + dx)) * CST];
#pragma unroll
            for (int c4 = 0; c4 < 4; c4++) {
                float4 v4 = *(const float4*)(vp + c4 * 4);
                acc[c4 * 4 + 0] += wt * v4.x;
                acc[c4 * 4 + 1] += wt * v4.y;
                acc[c4 * 4 + 2] += wt * v4.z;
                acc[c4 * 4 + 3] += wt * v4.w;
            }
        }
    }
#pragma unroll
    for (int j = 0; j < 15; j++) {
        float wt = lr[j];
        const float* vp = &Vs[((py + 7) * EWE + (px + j)) * CST];
#pragma unroll
        for (int c4 = 0; c4 < 4; c4++) {
            float4 v4 = *(const float4*)(vp + c4 * 4);
            acc[c4 * 4 + 0] += wt * v4.x;
            acc[c4 * 4 + 1] += wt * v4.y;
            acc[c4 * 4 + 2] += wt * v4.z;
            acc[c4 * 4 + 3] += wt * v4.w;
        }
    }
#pragma unroll
    for (int i = 0; i < 15; i++) {
        float wt = lc[i];
        const float* vp = &Vs[((py + i) * EWE + (px + 7)) * CST];
#pragma unroll
        for (int c4 = 0; c4 < 4; c4++) {
            float4 v4 = *(const float4*)(vp + c4 * 4);
            acc[c4 * 4 + 0] += wt * v4.x;
            acc[c4 * 4 + 1] += wt * v4.y;
            acc[c4 * 4 + 2] += wt * v4.z;
            acc[c4 * 4 + 3] += wt * v4.w;
        }
    }

    // ---- write output (B, 128, 64, 64) ----
    float* op = out + (size_t)(b * NCH + ch0) * 4096 + h * WW + w;
#pragma unroll
    for (int c = 0; c < 16; c++) op[(size_t)c * 4096] = acc[c];
}

// ---------------------------------------------------------------------------
extern "C" void kernel_launch(void* const* d_in, const int* in_sizes, int n_in,
                              void* d_out, int out_size)
{
    const float* fm   = (const float*)d_in[0];
    const float* wq   = (const float*)d_in[1];
    const float* wk   = (const float*)d_in[2];
    const float* wv   = (const float*)d_in[3];
    const float* relh = (const float*)d_in[4];
    const float* relw = (const float*)d_in[5];
    float* out = (float*)d_out;

    const int smem_bytes = 2 * EHE * EWE * CST * (int)sizeof(float);  // 105600
    cudaFuncSetAttribute(attn_kernel,
                         cudaFuncAttributeMaxDynamicSharedMemorySize, smem_bytes);

    conv_gemm_kernel<<<dim3(NPOS / 64, 2, 3), 256>>>(fm, wq, wk, wv);
    attn_kernel<<<dim3(WW / TILE_W, HH / TILE_H, BB * 8), 128, smem_bytes>>>(
        relh, relw, out);
}

// round 2
// speedup vs baseline: 1.1207x; 1.1207x over previous
#include <cuda_runtime.h>

// ---------------------------------------------------------------------------
// Temporal attention, B=2, H=W=64, C=128, GROUPS=8 (cg=16), K=7, PAD=3, REFINE
// Stage 1: conv1x1 GEMMs -> g_Q, g_K, g_V   (layout [ch][b*4096 + h*64 + w])
// Stage 2: fused windowed attention, online softmax, 16x32 tile / 512 threads
// ---------------------------------------------------------------------------

#define HH   64
#define WW   64
#define BB   2
#define NCH  128
#define NPOS 8192            // BB*HH*WW

__device__ float g_Q[NCH * NPOS];
__device__ float g_K[NCH * NPOS];
__device__ float g_V[NCH * NPOS];

// ---------------------------------------------------------------------------
// Stage 1: C[o][p] = sum_c W[o][c] * X[c][p]   (z: 0=K,1=V,2=Q)
// ---------------------------------------------------------------------------
__global__ void __launch_bounds__(256) conv_gemm_kernel(
    const float* __restrict__ fm,
    const float* __restrict__ wq,
    const float* __restrict__ wk,
    const float* __restrict__ wv)
{
    const int z = blockIdx.z;
    const float* Wm = (z == 0) ? wk : (z == 1) ? wv : wq;
    float* C        = (z == 0) ? g_K : (z == 1) ? g_V : g_Q;
    const int cbase = (z == 2) ? 128 : 0;

    const int p0 = blockIdx.x * 64;
    const int o0 = blockIdx.y * 64;
    const int b   = p0 >> 12;
    const int hw0 = p0 & 4095;
    const float* Xbase = fm + (size_t)b * (256 * 4096) + (size_t)cbase * 4096 + hw0;

    __shared__ float As[16][68];
    __shared__ float Bs[16][64];

    const int tid  = threadIdx.x;
    const int tx   = tid & 15;
    const int ty   = tid >> 4;
    const int a_row = tid >> 2, a_kg = tid & 3;
    const int b_row = tid >> 4, b_cg = tid & 15;

    float acc[4][4];
#pragma unroll
    for (int i = 0; i < 4; i++)
#pragma unroll
        for (int j = 0; j < 4; j++) acc[i][j] = 0.f;

    for (int k0 = 0; k0 < 128; k0 += 16) {
        float4 aw = *(const float4*)(Wm + (o0 + a_row) * 128 + k0 + a_kg * 4);
        As[a_kg * 4 + 0][a_row] = aw.x;
        As[a_kg * 4 + 1][a_row] = aw.y;
        As[a_kg * 4 + 2][a_row] = aw.z;
        As[a_kg * 4 + 3][a_row] = aw.w;
        *(float4*)&Bs[b_row][b_cg * 4] =
            *(const float4*)(Xbase + (size_t)(k0 + b_row) * 4096 + b_cg * 4);
        __syncthreads();
#pragma unroll
        for (int kk = 0; kk < 16; kk++) {
            float4 a  = *(const float4*)&As[kk][ty * 4];
            float4 bq = *(const float4*)&Bs[kk][tx * 4];
            acc[0][0] += a.x * bq.x; acc[0][1] += a.x * bq.y;
            acc[0][2] += a.x * bq.z; acc[0][3] += a.x * bq.w;
            acc[1][0] += a.y * bq.x; acc[1][1] += a.y * bq.y;
            acc[1][2] += a.y * bq.z; acc[1][3] += a.y * bq.w;
            acc[2][0] += a.z * bq.x; acc[2][1] += a.z * bq.y;
            acc[2][2] += a.z * bq.z; acc[2][3] += a.z * bq.w;
            acc[3][0] += a.w * bq.x; acc[3][1] += a.w * bq.y;
            acc[3][2] += a.w * bq.z; acc[3][3] += a.w * bq.w;
        }
        __syncthreads();
    }

    float* Cp = C + (size_t)(o0 + ty * 4) * NPOS + p0 + tx * 4;
#pragma unroll
    for (int i = 0; i < 4; i++) {
        float4 v = make_float4(acc[i][0], acc[i][1], acc[i][2], acc[i][3]);
        *(float4*)(Cp + (size_t)i * NPOS) = v;
    }
}

// ---------------------------------------------------------------------------
// Stage 2: attention, online softmax. Block = (b, g, 16x32 spatial tile),
// 512 threads (1 thr = 1 position). K/V tiles with +/-7 halo in smem, layout
// [pos][c] with 20-float stride (16B aligned -> conflict-free LDS.128 phases).
// ---------------------------------------------------------------------------
#define TILE_H 16
#define TILE_W 32
#define EHE    (TILE_H + 14)   // 30
#define EWE    (TILE_W + 14)   // 46
#define CST    20

__global__ void __launch_bounds__(512, 1) attn_kernel(
    const float* __restrict__ relh,
    const float* __restrict__ relw,
    float* __restrict__ out)
{
    extern __shared__ float sm[];
    float* Ks = sm;
    float* Vs = sm + EHE * EWE * CST;

    const int bz = blockIdx.z;          // b*8 + g
    const int b  = bz >> 3;
    const int g  = bz & 7;
    const int y0 = blockIdx.y * TILE_H;
    const int x0 = blockIdx.x * TILE_W;
    const int ch0 = g * 16;
    const int tid = threadIdx.x;

    // ---- load extended K/V tiles (zero outside image); rows are (c,yy) ----
    const float* Kbase = g_K + (size_t)ch0 * NPOS + b * 4096;
    const float* Vbase = g_V + (size_t)ch0 * NPOS + b * 4096;
    for (int idx = tid; idx < 16 * EHE * EWE; idx += 512) {
        int row = idx / EWE;            // c*EHE + yy
        int xx  = idx - row * EWE;
        int c   = row / EHE;
        int yy  = row - c * EHE;
        int gy = y0 + yy - 7, gx = x0 + xx - 7;
        float kv = 0.f, vv = 0.f;
        if ((unsigned)gy < (unsigned)HH && (unsigned)gx < (unsigned)WW) {
            int off = c * NPOS + gy * WW + gx;
            kv = Kbase[off];
            vv = Vbase[off];
        }
        int s = (yy * EWE + xx) * CST + c;
        Ks[s] = kv;
        Vs[s] = vv;
    }
    __syncthreads();

    const int px = tid & 31, py = tid >> 5;
    const int h = y0 + py, w = x0 + px;

    // ---- per-thread query ----
    float q[16];
    const float* Qp = g_Q + (size_t)ch0 * NPOS + b * 4096 + h * WW + w;
#pragma unroll
    for (int c = 0; c < 16; c++) q[c] = Qp[(size_t)c * NPOS];

    // ---- rel bias: g<4 -> rel_h (by dy), g>=4 -> rel_w (by dx) ----
    const bool use_h = (g < 4);
    const float* rel = use_h ? (relh + ch0 * 7) : (relw + (ch0 - 64) * 7);
    float bias[7];
#pragma unroll
    for (int i = 0; i < 7; i++) {
        float s = 0.f;
#pragma unroll
        for (int c = 0; c < 16; c++) s += q[c] * __ldg(&rel[c * 7 + i]);
        bias[i] = s;
    }

    float outv[16];
#pragma unroll
    for (int c = 0; c < 16; c++) outv[c] = 0.f;

    float vacc[16];
    float m, ssum;

    // ================= branch A: 2D 7x7 window (with rel bias) =============
    m = -1e30f; ssum = 0.f;
#pragma unroll
    for (int c = 0; c < 16; c++) vacc[c] = 0.f;
#pragma unroll
    for (int dy = 0; dy < 7; dy++) {
#pragma unroll
        for (int dx = 0; dx < 7; dx++) {
            const int p = (py + 4 + dy) * EWE + (px + 4 + dx);
            const float* kp = &Ks[p * CST];
            float l = use_h ? bias[dy] : bias[dx];
#pragma unroll
            for (int c4 = 0; c4 < 4; c4++) {
                float4 k4 = *(const float4*)(kp + c4 * 4);
                l += q[c4 * 4 + 0] * k4.x + q[c4 * 4 + 1] * k4.y +
                     q[c4 * 4 + 2] * k4.z + q[c4 * 4 + 3] * k4.w;
            }
            if (l > m) {
                float cor = __expf(m - l);
                ssum *= cor;
#pragma unroll
                for (int c = 0; c < 16; c++) vacc[c] *= cor;
                m = l;
            }
            float e = __expf(l - m);
            ssum += e;
            const float* vp = &Vs[p * CST];
#pragma unroll
            for (int c4 = 0; c4 < 4; c4++) {
                float4 v4 = *(const float4*)(vp + c4 * 4);
                vacc[c4 * 4 + 0] += e * v4.x;
                vacc[c4 * 4 + 1] += e * v4.y;
                vacc[c4 * 4 + 2] += e * v4.z;
                vacc[c4 * 4 + 3] += e * v4.w;
            }
        }
    }
    {
        float inv = 1.f / ssum;
#pragma unroll
        for (int c = 0; c < 16; c++) outv[c] += vacc[c] * inv;
    }

    // ================= branch B: row window (15 along x) ===================
    m = -1e30f; ssum = 0.f;
#pragma unroll
    for (int c = 0; c < 16; c++) vacc[c] = 0.f;
#pragma unroll
    for (int j = 0; j < 15; j++) {
        const int p = (py + 7) * EWE + (px + j);
        const float* kp = &Ks[p * CST];
        float l = 0.f;
#pragma unroll
        for (int c4 = 0; c4 < 4; c4++) {
            float4 k4 = *(const float4*)(kp + c4 * 4);
            l += q[c4 * 4 + 0] * k4.x + q[c4 * 4 + 1] * k4.y +
                 q[c4 * 4 + 2] * k4.z + q[c4 * 4 + 3] * k4.w;
        }
        if (l > m) {
            float cor = __expf(m - l);
            ssum *= cor;
#pragma unroll
            for (int c = 0; c < 16; c++) vacc[c] *= cor;
            m = l;
        }
        float e = __expf(l - m);
        ssum += e;
        const float* vp = &Vs[p * CST];
#pragma unroll
        for (int c4 = 0; c4 < 4; c4++) {
            float4 v4 = *(const float4*)(vp + c4 * 4);
            vacc[c4 * 4 + 0] += e * v4.x;
            vacc[c4 * 4 + 1] += e * v4.y;
            vacc[c4 * 4 + 2] += e * v4.z;
            vacc[c4 * 4 + 3] += e * v4.w;
        }
    }
    {
        float inv = 1.f / ssum;
#pragma unroll
        for (int c = 0; c < 16; c++) outv[c] += vacc[c] * inv;
    }

    // ================= branch C: col window (15 along y) ===================
    m = -1e30f; ssum = 0.f;
#pragma unroll
    for (int c = 0; c < 16; c++) vacc[c] = 0.f;
#pragma unroll
    for (int i = 0; i < 15; i++) {
        const int p = (py + i) * EWE + (px + 7);
        const float* kp = &Ks[p * CST];
        float l = 0.f;
#pragma unroll
        for (int c4 = 0; c4 < 4; c4++) {
            float4 k4 = *(const float4*)(kp + c4 * 4);
            l += q[c4 * 4 + 0] * k4.x + q[c4 * 4 + 1] * k4.y +
                 q[c4 * 4 + 2] * k4.z + q[c4 * 4 + 3] * k4.w;
        }
        if (l > m) {
            float cor = __expf(m - l);
            ssum *= cor;
#pragma unroll
            for (int c = 0; c < 16; c++) vacc[c] *= cor;
            m = l;
        }
        float e = __expf(l - m);
        ssum += e;
        const float* vp = &Vs[p * CST];
#pragma unroll
        for (int c4 = 0; c4 < 4; c4++) {
            float4 v4 = *(const float4*)(vp + c4 * 4);
            vacc[c4 * 4 + 0] += e * v4.x;
            vacc[c4 * 4 + 1] += e * v4.y;
            vacc[c4 * 4 + 2] += e * v4.z;
            vacc[c4 * 4 + 3] += e * v4.w;
        }
    }
    {
        float inv = 1.f / ssum;
#pragma unroll
        for (int c = 0; c < 16; c++) outv[c] += vacc[c] * inv;
    }

    // ---- write output (B, 128, 64, 64) ----
    float* op = out + (size_t)(b * NCH + ch0) * 4096 + h * WW + w;
#pragma unroll
    for (int c = 0; c < 16; c++) op[(size_t)c * 4096] = outv[c];
}

// ---------------------------------------------------------------------------
extern "C" void kernel_launch(void* const* d_in, const int* in_sizes, int n_in,
                              void* d_out, int out_size)
{
    const float* fm   = (const float*)d_in[0];
    const float* wq   = (const float*)d_in[1];
    const float* wk   = (const float*)d_in[2];
    const float* wv   = (const float*)d_in[3];
    const float* relh = (const float*)d_in[4];
    const float* relw = (const float*)d_in[5];
    float* out = (float*)d_out;

    const int smem_bytes = 2 * EHE * EWE * CST * (int)sizeof(float);  // 220800
    cudaFuncSetAttribute(attn_kernel,
                         cudaFuncAttributeMaxDynamicSharedMemorySize, smem_bytes);

    conv_gemm_kernel<<<dim3(NPOS / 64, 2, 3), 256>>>(fm, wq, wk, wv);
    attn_kernel<<<dim3(WW / TILE_W, HH / TILE_H, BB * 8), 512, smem_bytes>>>(
        relh, relw, out);
}